// round 12
// baseline (speedup 1.0000x reference)
#include <cuda_runtime.h>
#include <cuda_fp16.h>
#include <math.h>

// KDLayerNorm: per-row kernel-density CDF -> Gaussian PPF normalization.
// 2*cdf_i - 1 = (1/D) * sum_j erf((x_i-x_j)/(bw*sqrt2))
// erf(t) ~= tanh(t * q(min(t^2,12.25))), q quadratic, f16x2 + tanh.approx.f16x2.
// TWO DATA ROWS PER CTA (256 threads): f16x2 lanes = {row A, row B} at same
// column -> antisymmetric exchange is a pure shift mod 256, wrap via AND
// (no half-swap, no duplicated mirror region, minimal smem for occupancy).

#define DD 256
#define TB 256             // threads per block (one column each, 2 rows)
#define CW 16              // offsets per exchange chunk
#define NCH 8              // chunks cover d = 0..127 (d=0 contributes zeros)

__device__ __forceinline__ float kdln_tanhf(float x) {
    float y; asm("tanh.approx.f32 %0, %1;" : "=f"(y) : "f"(x)); return y;
}
__device__ __forceinline__ __half2 kdln_tanh2(__half2 x) {
    unsigned int xi = *(unsigned int*)&x, ri;
    asm("tanh.approx.f16x2 %0, %1;" : "=r"(ri) : "r"(xi));
    return *(__half2*)&ri;
}
typedef unsigned long long u64;
__device__ __forceinline__ u64 kdln_add2(u64 a, u64 b) {
    u64 r; asm("add.rn.f32x2 %0, %1, %2;" : "=l"(r) : "l"(a), "l"(b)); return r;
}
__device__ __forceinline__ u64 kdln_pack2(float lo, float hi) {
    u64 r; asm("mov.b64 %0, {%1, %2};" : "=l"(r) : "f"(lo), "f"(hi)); return r;
}
__device__ __forceinline__ void kdln_unpack2(u64 v, float& lo, float& hi) {
    asm("mov.b64 {%0, %1}, %2;" : "=f"(lo), "=f"(hi) : "l"(v));
}

// atanh(erf(x))/x quadratic-in-x^2 fit (interp at s=0, 2.25, 9; s clamped at 12.25)
#define QC0 1.1283792f
#define QC1 0.104728f
#define QC2 (-0.00208245f)
#define SMAX 12.25f

__global__ __launch_bounds__(TB, 8)
void kdln_kernel(const float* __restrict__ x,
                 const float* __restrict__ weight,
                 const float* __restrict__ bias,
                 float* __restrict__ out)
{
    __shared__ u64 syw[DD + 128];             // word k = {-xsA_k, -xsB_k}, wrap-extended (3KB)
    __shared__ unsigned int sfh[CW][DD];      // exchange f16x2 {eA,eB}, index = j (16KB)
    __shared__ float red[8][4];

    const int rowA = blockIdx.x * 2;
    const int t    = threadIdx.x;

    const float vA = x[rowA * DD + t];
    const float vB = x[rowA * DD + DD + t];

    // --- per-row mean / var (ddof=1), both rows at once ---
    float sA = vA, qA = vA * vA, sB = vB, qB = vB * vB;
    #pragma unroll
    for (int o = 16; o > 0; o >>= 1) {
        sA += __shfl_xor_sync(0xFFFFFFFFu, sA, o);
        qA += __shfl_xor_sync(0xFFFFFFFFu, qA, o);
        sB += __shfl_xor_sync(0xFFFFFFFFu, sB, o);
        qB += __shfl_xor_sync(0xFFFFFFFFu, qB, o);
    }
    if ((t & 31) == 0) {
        red[t >> 5][0] = sA; red[t >> 5][1] = qA;
        red[t >> 5][2] = sB; red[t >> 5][3] = qB;
    }
    __syncthreads();

    float SA = 0.f, QA = 0.f, SB = 0.f, QB = 0.f;
    #pragma unroll
    for (int i = 0; i < 8; i++) {
        SA += red[i][0]; QA += red[i][1];
        SB += red[i][2]; QB += red[i][3];
    }

    const float meanA = SA * (1.0f / DD);
    const float meanB = SB * (1.0f / DD);
    const float varA  = (QA - (float)DD * meanA * meanA) * (1.0f / (DD - 1));
    const float varB  = (QB - (float)DD * meanB * meanB) * (1.0f / (DD - 1));
    // 1 / (0.9 * 256^(-0.2) * sqrt(2)) = 1 / 0.419866...
    const float invA = 1.0f / (0.419866213371f * sqrtf(varA));
    const float invB = 1.0f / (0.419866213371f * sqrtf(varB));

    const float mA = vA * invA;
    const float mB = vB * invB;
    const u64 negm = kdln_pack2(-mA, -mB);
    syw[t] = negm;
    if (t < 128) syw[t + DD] = negm;           // wrap extension for direct phase
    __syncthreads();

    const u64 my2 = kdln_pack2(mA, mB);
    const __half2 C0h = __float2half2_rn(QC0);
    const __half2 C1h = __float2half2_rn(QC1);
    const __half2 C2h = __float2half2_rn(QC2);
    const __half2 SMX = __float2half2_rn(SMAX);

    float accPA = 0.f, accPB = 0.f;   // direct terms  (j = t+1 .. t+127)
    float accMA = 0.f, accMB = 0.f;   // exchanged terms (j = t-1 .. t-127)

    for (int c = 0; c < NCH; c++) {
        const int dbase = c * CW;

        // --- compute phase: f16x2 erf {rowA,rowB} at offsets d = dbase..dbase+15 ---
        #pragma unroll
        for (int u4 = 0; u4 < CW / 4; u4++) {
            __half2 pacc = __float2half2_rn(0.0f);
            #pragma unroll
            for (int w = 0; w < 4; w++) {
                const int u = u4 * 4 + w;
                const int d = dbase + u;
                const u64 t2 = kdln_add2(my2, syw[t + d]);   // f32: no cancellation bias
                float t0, t1; kdln_unpack2(t2, t0, t1);
                const __half2 th = __floats2half2_rn(t0, t1);
                __half2 sq = __hmul2(th, th);
                sq = __hmin2(sq, SMX);
                __half2 q = __hfma2(sq, C2h, C1h);
                q = __hfma2(q, sq, C0h);
                const __half2 e = kdln_tanh2(__hmul2(q, th));
                sfh[u][t] = *(const unsigned int*)&e;        // single store, index = own column
                pacc = __hadd2(pacc, e);
            }
            const float2 pf = __half22float2(pacc);
            accPA += pf.x;
            accPB += pf.y;
        }
        __syncthreads();

        // --- exchange phase: -f_d((t-d) mod 256) = -sfh[u][(t-d)&255]; no half-swap ---
        #pragma unroll
        for (int u4 = 0; u4 < CW / 4; u4++) {
            __half2 hacc = __float2half2_rn(0.0f);
            #pragma unroll
            for (int w = 0; w < 4; w++) {
                const int u = u4 * 4 + w;
                const unsigned int g = sfh[u][(t - dbase - u) & (DD - 1)];
                hacc = __hadd2(hacc, *(const __half2*)&g);
            }
            const float2 gf = __half22float2(hacc);
            accMA += gf.x;
            accMB += gf.y;
        }
        __syncthreads();   // sfh reused next chunk
    }

    // --- d = 128 term: direct only (each thread adds its own signed term) ---
    float y128A, y128B;
    kdln_unpack2(syw[t + 128], y128A, y128B);  // = {-xsA_{(t+128)%256}, -xsB_{(t+128)%256}}
    const float tA = mA + y128A;
    const float tB = mB + y128B;
    const float sA2 = fminf(tA * tA, SMAX);
    const float sB2 = fminf(tB * tB, SMAX);
    const float eA = kdln_tanhf(fmaf(fmaf(QC2, sA2, QC1), sA2, QC0) * tA);
    const float eB = kdln_tanhf(fmaf(fmaf(QC2, sB2, QC1), sB2, QC0) * tB);

    const float accA = accPA - accMA + eA;
    const float accB = accPB - accMB + eB;

    // 2*cdf - 1 = acc / D
    const float nA = erfinvf(accA * (1.0f / DD)) * 1.4142135623730951f;
    const float nB = erfinvf(accB * (1.0f / DD)) * 1.4142135623730951f;
    const float wt = weight[t];
    const float bs = bias[t];
    out[rowA * DD + t]      = nA * wt + bs;
    out[rowA * DD + DD + t] = nB * wt + bs;
}

extern "C" void kernel_launch(void* const* d_in, const int* in_sizes, int n_in,
                              void* d_out, int out_size)
{
    const float* x = (const float*)d_in[0];
    const float* w = (const float*)d_in[1];
    const float* b = (const float*)d_in[2];
    float* out = (float*)d_out;

    const int n_rows = in_sizes[0] / DD;   // 4096
    kdln_kernel<<<n_rows / 2, TB>>>(x, w, b, out);
}

// round 13
// speedup vs baseline: 1.1187x; 1.1187x over previous
#include <cuda_runtime.h>
#include <cuda_fp16.h>
#include <math.h>

// KDLayerNorm via Fourier factorization.
// 2*cdf_i - 1 = (1/D) * sum_j erf(xs_i - xs_j),  xs = x/(bw*sqrt2)
// erf(t) = t/L + sum_k beta_k sin(k*pi*t/L)  (L=14, K=24, beta exact closed form)
// => sum_j erf(xs_i-xs_j) = (D*xs_i - SX)/L + sum_k beta_k [s_k(i)C_k - c_k(i)S_k]
// O(D*K) instead of O(D^2). Rotation recurrence for s_k,c_k; block reduction
// for C_k,S_k (modes 1-4 f32 shuffles, 5-24 packed f16x2 shuffles).

#define D 256
#define K 24
#define NW 8
#define TH1 0.224399475f          // pi/14
#define LINV 0.0714285714f        // 1/14

__constant__ float BETA[K] = {
    0.6286574f, 0.3026776f, 0.1894773f, 0.1301196f,
    0.0929447f, 0.0674381f, 0.0490777f, 0.0355518f,
    0.0255159f, 0.0180787f, 0.0126153f, 0.0086588f,
    0.0058343f, 0.0038574f, 0.0025003f, 0.0015860f,
    0.0009855f, 0.0005977f, 0.0003563f, 0.0002069f,
    0.0001182f, 0.0000652f, 0.0000355f, 0.0000189f
};

__global__ __launch_bounds__(D, 8)
void kdln_kernel(const float* __restrict__ x,
                 const float* __restrict__ weight,
                 const float* __restrict__ bias,
                 float* __restrict__ out)
{
    __shared__ float sC[K][NW];    // per-warp partial sums of cos(theta_k * xs_j)
    __shared__ float sS[K][NW];    // per-warp partial sums of sin(theta_k * xs_j)
    __shared__ float sCf[K];       // beta_k * C_k
    __shared__ float sSf[K];       // beta_k * S_k
    __shared__ float red[NW][2];

    const int row  = blockIdx.x;
    const int t    = threadIdx.x;
    const int lane = t & 31;
    const int wid  = t >> 5;

    const float v = x[row * D + t];

    // --- row mean / var (ddof=1) ---
    float s = v, q = v * v;
    #pragma unroll
    for (int o = 16; o > 0; o >>= 1) {
        s += __shfl_xor_sync(0xFFFFFFFFu, s, o);
        q += __shfl_xor_sync(0xFFFFFFFFu, q, o);
    }
    if (lane == 0) { red[wid][0] = s; red[wid][1] = q; }
    __syncthreads();

    float S = 0.f, Q = 0.f;
    #pragma unroll
    for (int i = 0; i < NW; i++) { S += red[i][0]; Q += red[i][1]; }

    const float mean = S * (1.0f / D);
    const float var  = (Q - (float)D * mean * mean) * (1.0f / (D - 1));
    // bw*sqrt2 = 0.9*256^(-0.2)*sqrt(2)*std = 0.419866*std
    const float inv  = 1.0f / (0.419866213f * sqrtf(var));

    const float xs = v * inv;
    const float SX = S * inv;

    const float phi = TH1 * xs;
    const float s1 = __sinf(phi);
    const float c1 = __cosf(phi);

    // --- pass 1: generate s_k, c_k; block-reduce into per-warp partials ---
    {
        float sk = s1, ck = c1;
        #pragma unroll
        for (int k = 0; k < K; k++) {
            if (k > 0) {
                const float ns = fmaf(sk, c1,  ck * s1);
                const float nc = fmaf(ck, c1, -sk * s1);
                sk = ns; ck = nc;
            }
            if (k < 4) {
                // f32 reduction for the high-sensitivity low modes
                float ws = sk, wc = ck;
                #pragma unroll
                for (int o = 16; o > 0; o >>= 1) {
                    ws += __shfl_xor_sync(0xFFFFFFFFu, ws, o);
                    wc += __shfl_xor_sync(0xFFFFFFFFu, wc, o);
                }
                if (lane == k) { sS[k][wid] = ws; sC[k][wid] = wc; }
            } else {
                // packed f16x2 reduction {sin, cos}
                __half2 h = __floats2half2_rn(sk, ck);
                unsigned int u = *(const unsigned int*)&h;
                #pragma unroll
                for (int o = 16; o > 0; o >>= 1) {
                    const unsigned int up = __shfl_xor_sync(0xFFFFFFFFu, u, o);
                    const __half2 hp = *(const __half2*)&up;
                    const __half2 hu = *(const __half2*)&u;
                    const __half2 hr = __hadd2(hu, hp);
                    u = *(const unsigned int*)&hr;
                }
                if (lane == k) {
                    const __half2 hr = *(const __half2*)&u;
                    const float2 f = __half22float2(hr);
                    sS[k][wid] = f.x;
                    sC[k][wid] = f.y;
                }
            }
        }
    }
    __syncthreads();

    // --- final cross-warp sums, scaled by beta (threads 0..2K-1) ---
    if (t < 2 * K) {
        const int m = t >> 1;
        float a = 0.f;
        if (t & 1) {
            #pragma unroll
            for (int w = 0; w < NW; w++) a += sS[m][w];
            sSf[m] = BETA[m] * a;
        } else {
            #pragma unroll
            for (int w = 0; w < NW; w++) a += sC[m][w];
            sCf[m] = BETA[m] * a;
        }
    }
    __syncthreads();

    // --- pass 2: combine ---
    float R = (256.0f * xs - SX) * LINV;
    {
        float sk = s1, ck = c1;
        #pragma unroll
        for (int k = 0; k < K; k++) {
            if (k > 0) {
                const float ns = fmaf(sk, c1,  ck * s1);
                const float nc = fmaf(ck, c1, -sk * s1);
                sk = ns; ck = nc;
            }
            R = fmaf(sk,  sCf[k], R);
            R = fmaf(-ck, sSf[k], R);
        }
    }

    // 2*cdf - 1 = R / D
    const float nrm = erfinvf(R * (1.0f / D)) * 1.4142135623730951f;
    out[row * D + t] = nrm * weight[t] + bias[t];
}

extern "C" void kernel_launch(void* const* d_in, const int* in_sizes, int n_in,
                              void* d_out, int out_size)
{
    const float* x = (const float*)d_in[0];
    const float* w = (const float*)d_in[1];
    const float* b = (const float*)d_in[2];
    float* out = (float*)d_out;

    const int n_rows = in_sizes[0] / D;   // 4096
    kdln_kernel<<<n_rows, D>>>(x, w, b, out);
}

// round 14
// speedup vs baseline: 2.4222x; 2.1653x over previous
#include <cuda_runtime.h>
#include <math.h>

// KDLayerNorm via Fourier factorization, warp-specialized mode reduction.
// 2*cdf_i - 1 = (1/D) * sum_j erf(xs_i - xs_j),  xs = x/(bw*sqrt2)
// erf(t) = t/L + sum_k beta_k sin(k*pi*t/L)  (L=14, K=24, exact closed-form beta)
// => sum_j erf(xs_i-xs_j) = (D*xs_i - SX)/L + sum_k beta_k [s_k(i)C_k - c_k(i)S_k]
// Pass 1: warp w computes modes {3w+1..3w+3}: C_k,S_k = sums over staged xs via
//         MUFU sincos, f32 accumulation, one warp reduction per mode.
// Pass 2: per-element rotation recurrence (FMA) combines with beta-scaled sums.

#define D 256
#define K 24
#define NW 8
#define TH1 0.2243994753f         // pi/14
#define LINV 0.0714285714f        // 1/14

__constant__ float BETA[K] = {
    0.6286574f, 0.3026776f, 0.1894773f, 0.1301196f,
    0.0929447f, 0.0674381f, 0.0490777f, 0.0355518f,
    0.0255159f, 0.0180787f, 0.0126153f, 0.0086588f,
    0.0058343f, 0.0038574f, 0.0025003f, 0.0015860f,
    0.0009855f, 0.0005977f, 0.0003563f, 0.0002069f,
    0.0001182f, 0.0000652f, 0.0000355f, 0.0000189f
};

__global__ __launch_bounds__(D, 8)
void kdln_kernel(const float* __restrict__ x,
                 const float* __restrict__ weight,
                 const float* __restrict__ bias,
                 float* __restrict__ out)
{
    __shared__ __align__(16) float sxs[D];   // staged scaled row
    __shared__ float2 scs[K];                // {beta*C_k, beta*S_k}
    __shared__ float red[NW][2];

    const int row  = blockIdx.x;
    const int t    = threadIdx.x;
    const int lane = t & 31;
    const int wid  = t >> 5;

    const float v = x[row * D + t];

    // --- row mean / var (ddof=1) ---
    float s = v, q = v * v;
    #pragma unroll
    for (int o = 16; o > 0; o >>= 1) {
        s += __shfl_xor_sync(0xFFFFFFFFu, s, o);
        q += __shfl_xor_sync(0xFFFFFFFFu, q, o);
    }
    if (lane == 0) { red[wid][0] = s; red[wid][1] = q; }
    __syncthreads();

    float S = 0.f, Q = 0.f;
    #pragma unroll
    for (int i = 0; i < NW; i++) { S += red[i][0]; Q += red[i][1]; }

    const float mean = S * (1.0f / D);
    const float var  = (Q - (float)D * mean * mean) * (1.0f / (D - 1));
    // bw*sqrt2 = 0.9*256^(-0.2)*sqrt(2)*std = 0.419866*std
    const float inv  = 1.0f / (0.419866213f * sqrtf(var));

    const float xs = v * inv;
    const float SX = S * inv;

    sxs[t] = xs;
    __syncthreads();

    // --- pass 1: warp-specialized mode sums ---
    // warp w handles modes k = 3w+1, 3w+2, 3w+3 (array idx 3w..3w+2)
    {
        const float4* p4 = (const float4*)sxs;
        const float4 a = p4[lane * 2];
        const float4 b = p4[lane * 2 + 1];

        #pragma unroll
        for (int m = 0; m < 3; m++) {
            const int ki = 3 * wid + m;        // 0..23 -> k = ki+1
            const float th = (float)(ki + 1) * TH1;
            float as = 0.f, ac = 0.f;
            {
                float p;
                p = th * a.x; as += __sinf(p); ac += __cosf(p);
                p = th * a.y; as += __sinf(p); ac += __cosf(p);
                p = th * a.z; as += __sinf(p); ac += __cosf(p);
                p = th * a.w; as += __sinf(p); ac += __cosf(p);
                p = th * b.x; as += __sinf(p); ac += __cosf(p);
                p = th * b.y; as += __sinf(p); ac += __cosf(p);
                p = th * b.z; as += __sinf(p); ac += __cosf(p);
                p = th * b.w; as += __sinf(p); ac += __cosf(p);
            }
            #pragma unroll
            for (int o = 16; o > 0; o >>= 1) {
                as += __shfl_xor_sync(0xFFFFFFFFu, as, o);
                ac += __shfl_xor_sync(0xFFFFFFFFu, ac, o);
            }
            if (lane == 0) {
                const float bk = BETA[ki];
                scs[ki] = make_float2(bk * ac, bk * as);   // {beta*C, beta*S}
            }
        }
    }
    __syncthreads();

    // --- pass 2: per-element combine via rotation recurrence ---
    const float phi = TH1 * xs;
    const float s1 = __sinf(phi);
    const float c1 = __cosf(phi);

    float R = (256.0f * xs - SX) * LINV;
    {
        float sk = s1, ck = c1;
        #pragma unroll
        for (int ki = 0; ki < K; ki++) {
            if (ki > 0) {
                const float ns = fmaf(sk, c1,  ck * s1);
                const float nc = fmaf(ck, c1, -sk * s1);
                sk = ns; ck = nc;
            }
            const float2 cs = scs[ki];
            R = fmaf(sk,  cs.x, R);
            R = fmaf(-ck, cs.y, R);
        }
    }

    // 2*cdf - 1 = R / D
    const float nrm = erfinvf(R * (1.0f / D)) * 1.4142135623730951f;
    out[row * D + t] = nrm * weight[t] + bias[t];
}

extern "C" void kernel_launch(void* const* d_in, const int* in_sizes, int n_in,
                              void* d_out, int out_size)
{
    const float* x = (const float*)d_in[0];
    const float* w = (const float*)d_in[1];
    const float* b = (const float*)d_in[2];
    float* out = (float*)d_out;

    const int n_rows = in_sizes[0] / D;   // 4096
    kdln_kernel<<<n_rows, D>>>(x, w, b, out);
}

// round 15
// speedup vs baseline: 2.9067x; 1.2000x over previous
#include <cuda_runtime.h>
#include <math.h>

// KDLayerNorm via Fourier factorization, warp-specialized mode reduction.
// 2*cdf_i - 1 = (1/D) * sum_j erf(xs_i - xs_j),  xs = x/(bw*sqrt2)
// erf(t) = t/L + sum_k beta_k sin(k*pi*t/L),  L=13, K=16 (valid |t| <= 2L-4 = 22)
// => sum_j erf = (D*xs_i - SX)/L + sum_k beta_k [s_k(i)C_k - c_k(i)S_k]
// Pass 1: warp w computes modes {2w+1, 2w+2} over the staged row (MUFU sincos,
//         f32 accumulation, one warp reduction per mode).
// Pass 2: rotation recurrence combine; fast single-branch Giles erfinv epilogue
//         (cdf in [0.5/256, 1-0.5/256] guarantees the central branch).

#define D 256
#define K 16
#define NW 8
#define TH1 0.2416609734f         // pi/13
#define LINV 0.0769230769f        // 1/13

__constant__ float BETA[K] = {
    0.62740f,  0.30025f,  0.18608f,  0.12600f,
    0.08838f,  0.06273f,  0.04447f,  0.03126f,
    0.02168f,  0.01478f,  0.00990f,  0.00648f,
    0.00415f,  0.00260f,  0.00159f,  0.00095f
};

__device__ __forceinline__ float erfinv_fast(float x) {
    // Giles (2010) central branch; valid for w = -ln(1-x^2) < 5 (|x| < 0.9966).
    float w = -__logf(fmaf(-x, x, 1.0f));
    w = w - 2.5f;
    float p =  2.81022636e-08f;
    p = fmaf(p, w,  3.43273939e-07f);
    p = fmaf(p, w, -3.5233877e-06f);
    p = fmaf(p, w, -4.39150654e-06f);
    p = fmaf(p, w,  2.1858087e-04f);
    p = fmaf(p, w, -1.25372503e-03f);
    p = fmaf(p, w, -4.17768164e-03f);
    p = fmaf(p, w,  2.46640727e-01f);
    p = fmaf(p, w,  1.50140941e+00f);
    return p * x;
}

__global__ __launch_bounds__(D, 8)
void kdln_kernel(const float* __restrict__ x,
                 const float* __restrict__ weight,
                 const float* __restrict__ bias,
                 float* __restrict__ out)
{
    __shared__ __align__(16) float sxs[D];       // staged scaled row
    __shared__ __align__(16) float2 scs[K];      // {beta*C_k, beta*S_k}
    __shared__ float red[NW][2];

    const int row  = blockIdx.x;
    const int t    = threadIdx.x;
    const int lane = t & 31;
    const int wid  = t >> 5;

    const float v = x[row * D + t];

    // --- row mean / var (ddof=1) ---
    float s = v, q = v * v;
    #pragma unroll
    for (int o = 16; o > 0; o >>= 1) {
        s += __shfl_xor_sync(0xFFFFFFFFu, s, o);
        q += __shfl_xor_sync(0xFFFFFFFFu, q, o);
    }
    if (lane == 0) { red[wid][0] = s; red[wid][1] = q; }
    __syncthreads();

    float S = 0.f, Q = 0.f;
    #pragma unroll
    for (int i = 0; i < NW; i++) { S += red[i][0]; Q += red[i][1]; }

    const float mean = S * (1.0f / D);
    const float var  = (Q - (float)D * mean * mean) * (1.0f / (D - 1));
    // bw*sqrt2 = 0.9*256^(-0.2)*sqrt(2)*std = 0.419866*std
    const float inv  = 1.0f / (0.419866213f * sqrtf(var));

    const float xs = v * inv;
    const float SX = S * inv;

    sxs[t] = xs;
    __syncthreads();

    // --- pass 1: warp-specialized mode sums (2 modes per warp, uniform) ---
    {
        const float4* p4 = (const float4*)sxs;
        const float4 a = p4[lane * 2];
        const float4 b = p4[lane * 2 + 1];

        #pragma unroll
        for (int m = 0; m < 2; m++) {
            const int ki = 2 * wid + m;        // 0..15 -> k = ki+1
            const float th = (float)(ki + 1) * TH1;
            float as = 0.f, ac = 0.f;
            {
                float p;
                p = th * a.x; as += __sinf(p); ac += __cosf(p);
                p = th * a.y; as += __sinf(p); ac += __cosf(p);
                p = th * a.z; as += __sinf(p); ac += __cosf(p);
                p = th * a.w; as += __sinf(p); ac += __cosf(p);
                p = th * b.x; as += __sinf(p); ac += __cosf(p);
                p = th * b.y; as += __sinf(p); ac += __cosf(p);
                p = th * b.z; as += __sinf(p); ac += __cosf(p);
                p = th * b.w; as += __sinf(p); ac += __cosf(p);
            }
            #pragma unroll
            for (int o = 16; o > 0; o >>= 1) {
                as += __shfl_xor_sync(0xFFFFFFFFu, as, o);
                ac += __shfl_xor_sync(0xFFFFFFFFu, ac, o);
            }
            if (lane == 0) {
                const float bk = BETA[ki];
                scs[ki] = make_float2(bk * ac, bk * as);   // {beta*C, beta*S}
            }
        }
    }
    __syncthreads();

    // --- pass 2: per-element combine via rotation recurrence (paired loads) ---
    const float phi = TH1 * xs;
    const float s1 = __sinf(phi);
    const float c1 = __cosf(phi);

    float R = (256.0f * xs - SX) * LINV;
    {
        const float4* scs4 = (const float4*)scs;   // {bC_k, bS_k, bC_{k+1}, bS_{k+1}}
        float sk = s1, ck = c1;                    // k = 1
        #pragma unroll
        for (int j = 0; j < K / 2; j++) {
            const float4 cs = scs4[j];
            R = fmaf(sk,  cs.x, R);
            R = fmaf(-ck, cs.y, R);
            {   // advance k -> k+1
                const float ns = fmaf(sk, c1,  ck * s1);
                const float nc = fmaf(ck, c1, -sk * s1);
                sk = ns; ck = nc;
            }
            R = fmaf(sk,  cs.z, R);
            R = fmaf(-ck, cs.w, R);
            if (j < K / 2 - 1) {   // advance k -> k+1 for next pair
                const float ns = fmaf(sk, c1,  ck * s1);
                const float nc = fmaf(ck, c1, -sk * s1);
                sk = ns; ck = nc;
            }
        }
    }

    // 2*cdf - 1 = R / D  (guaranteed in (-0.9962, 0.9962) + small truncation)
    float w2 = R * (1.0f / D);
    w2 = fminf(fmaxf(w2, -0.9965f), 0.9965f);
    const float nrm = erfinv_fast(w2) * 1.4142135623730951f;
    out[row * D + t] = nrm * weight[t] + bias[t];
}

extern "C" void kernel_launch(void* const* d_in, const int* in_sizes, int n_in,
                              void* d_out, int out_size)
{
    const float* x = (const float*)d_in[0];
    const float* w = (const float*)d_in[1];
    const float* b = (const float*)d_in[2];
    float* out = (float*)d_out;

    const int n_rows = in_sizes[0] / D;   // 4096
    kdln_kernel<<<n_rows, D>>>(x, w, b, out);
}